// round 10
// baseline (speedup 1.0000x reference)
#include <cuda_runtime.h>

#define IMG_H 2048
#define IMG_W 2048

constexpr int STRIP = 8;    // output rows per thread
constexpr int BLKT  = 128;  // threads per block, 4 cols each

// ---------- packed fp32x2 (sm_103a FFMA2/FADD2/FMUL2 via PTX) ----------
__device__ __forceinline__ float2 f2add(float2 a, float2 b) {
    unsigned long long ua = *reinterpret_cast<unsigned long long*>(&a);
    unsigned long long ub = *reinterpret_cast<unsigned long long*>(&b);
    unsigned long long ur;
    asm("add.rn.f32x2 %0, %1, %2;" : "=l"(ur) : "l"(ua), "l"(ub));
    return *reinterpret_cast<float2*>(&ur);
}
__device__ __forceinline__ float2 f2mul(float2 a, float2 b) {
    unsigned long long ua = *reinterpret_cast<unsigned long long*>(&a);
    unsigned long long ub = *reinterpret_cast<unsigned long long*>(&b);
    unsigned long long ur;
    asm("mul.rn.f32x2 %0, %1, %2;" : "=l"(ur) : "l"(ua), "l"(ub));
    return *reinterpret_cast<float2*>(&ur);
}
__device__ __forceinline__ float2 f2fma(float2 a, float2 b, float2 c) {  // a*b + c
    unsigned long long ua = *reinterpret_cast<unsigned long long*>(&a);
    unsigned long long ub = *reinterpret_cast<unsigned long long*>(&b);
    unsigned long long uc = *reinterpret_cast<unsigned long long*>(&c);
    unsigned long long ur;
    asm("fma.rn.f32x2 %0, %1, %2, %3;" : "=l"(ur) : "l"(ua), "l"(ub), "l"(uc));
    return *reinterpret_cast<float2*>(&ur);
}
__device__ __forceinline__ float2 f2sub(float2 a, float2 b) {  // a - b
    return f2fma(b, make_float2(-1.f, -1.f), a);
}

// ---------- horizontal window load + S/D compute ----------
__device__ __forceinline__ void load_row(const float* __restrict__ row, int gx0,
                                         bool interior, float4& a, float4& b, float4& c) {
    if (interior) {
        a = *reinterpret_cast<const float4*>(row + gx0 - 4);
        b = *reinterpret_cast<const float4*>(row + gx0);
        c = *reinterpret_cast<const float4*>(row + gx0 + 4);
    } else {
        float f[12];
        #pragma unroll
        for (int m = 0; m < 12; m++)
            f[m] = row[min(max(gx0 - 4 + m, 0), IMG_W - 1)];
        a = make_float4(f[0], f[1], f[2], f[3]);
        b = make_float4(f[4], f[5], f[6], f[7]);
        c = make_float4(f[8], f[9], f[10], f[11]);
    }
}

__device__ __forceinline__ void compute_sd(float4 a, float4 b, float4 c,
                                           float2& Sa, float2& Sb,
                                           float2& Da, float2& Db) {
    // window cols for output c0..c3: f1..f10 where f1=a.y ... f10=c.z
    float S0 = a.y + a.z + a.w + b.x + b.y + b.z + b.w;
    float S1 = S0 - a.y + c.x;
    float S2 = S1 - a.z + c.y;
    float S3 = S2 - a.w + c.z;
    float D0 = fmaf(-3.f, a.y, fmaf(-2.f, a.z, fmaf(2.f, b.z, fmaf(3.f, b.w, b.y - a.w))));
    float D1 = fmaf(3.f, a.y, fmaf(4.f, c.x, D0 - S1));
    float D2 = fmaf(3.f, a.z, fmaf(4.f, c.y, D1 - S2));
    float D3 = fmaf(3.f, a.w, fmaf(4.f, c.z, D2 - S3));
    Sa = make_float2(S0, S1);  Sb = make_float2(S2, S3);
    Da = make_float2(D0, D1);  Db = make_float2(D2, D3);
}

template <bool VFAST>
__device__ __forceinline__ void strip_run(const float* __restrict__ x,
                                          float* __restrict__ out,
                                          int gx0, int gy0, bool interior) {
    const float2 c3  = make_float2(3.f, 3.f);
    const float2 c4  = make_float2(4.f, 4.f);
    const float2 i196 = make_float2(1.f/196.f, 1.f/196.f);
    const float2 i49  = make_float2(1.f/49.f, 1.f/49.f);

    float2 rSa[7], rSb[7], rDa[7], rDb[7];

    const float* rp = x + (size_t)(VFAST ? (gy0 - 3) : 0) * IMG_W;

    // ---- warmup: extended rows e = 0..5 ----
    #pragma unroll
    for (int e = 0; e < 6; e++) {
        const float* row;
        if (VFAST) { row = rp; rp += IMG_W; }
        else row = x + (size_t)min(max(gy0 - 3 + e, 0), IMG_H - 1) * IMG_W;
        float4 a, b, c;
        load_row(row, gx0, interior, a, b, c);
        compute_sd(a, b, c, rSa[e], rSb[e], rDa[e], rDb[e]);
    }

    // ---- prefetch extended row e = 6 ----
    float4 na, nb, nc;
    {
        const float* row;
        if (VFAST) { row = rp; rp += IMG_W; }
        else row = x + (size_t)min(max(gy0 + 3, 0), IMG_H - 1) * IMG_W;
        load_row(row, gx0, interior, na, nb, nc);
    }

    float2 sSa, sSb, sYa, sYb, sDa, sDb;
    float* op = out + ((size_t)gy0 * IMG_W + gx0) * 3;

    #pragma unroll
    for (int r = 0; r < STRIP; r++) {
        const float4 ca = na, cb = nb, cc = nc;
        if (r + 1 < STRIP) {  // issue next row's loads before current row's math
            const float* row;
            if (VFAST) { row = rp; rp += IMG_W; }
            else row = x + (size_t)min(max(gy0 + 4 + r, 0), IMG_H - 1) * IMG_W;
            load_row(row, gx0, interior, na, nb, nc);
        }

        float2 Sna, Snb, Dna, Dnb;
        compute_sd(ca, cb, cc, Sna, Snb, Dna, Dnb);

        const int slot = (r + 6) % 7;   // compile-time under unroll
        if (r == 0) {
            rSa[6] = Sna; rSb[6] = Snb; rDa[6] = Dna; rDb[6] = Dnb;
            sSa = rSa[0]; sSb = rSb[0];
            sDa = rDa[0]; sDb = rDb[0];
            sYa = f2mul(rSa[0], make_float2(-3.f, -3.f));
            sYb = f2mul(rSb[0], make_float2(-3.f, -3.f));
            #pragma unroll
            for (int k = 1; k < 7; k++) {
                const float2 w = make_float2((float)(k - 3), (float)(k - 3));
                sSa = f2add(sSa, rSa[k]);  sSb = f2add(sSb, rSb[k]);
                sYa = f2fma(rSa[k], w, sYa);  sYb = f2fma(rSb[k], w, sYb);
                sDa = f2add(sDa, rDa[k]);  sDb = f2add(sDb, rDb[k]);
            }
        } else {
            const float2 Sla = rSa[slot], Slb = rSb[slot];
            const float2 Dla = rDa[slot], Dlb = rDb[slot];
            rSa[slot] = Sna; rSb[slot] = Snb;
            rDa[slot] = Dna; rDb[slot] = Dnb;
            // sY' = (sY - sS) + 4*S_leave + 3*S_enter  (uses OLD sS)
            sYa = f2fma(Sla, c4, f2fma(Sna, c3, f2sub(sYa, sSa)));
            sYb = f2fma(Slb, c4, f2fma(Snb, c3, f2sub(sYb, sSb)));
            sSa = f2add(f2sub(sSa, Sla), Sna);
            sSb = f2add(f2sub(sSb, Slb), Snb);
            sDa = f2add(f2sub(sDa, Dla), Dna);
            sDb = f2add(f2sub(sDb, Dlb), Dnb);
        }

        // ---- scale (packed) + interleave + 3 coalesced float4 stores ----
        const float2 dA = f2mul(sDa, i196), dB = f2mul(sDb, i196);
        const float2 yA = f2mul(sYa, i196), yB = f2mul(sYb, i196);
        const float2 sA = f2mul(sSa, i49),  sB = f2mul(sSb, i49);

        const float4 p0 = make_float4(dA.x, yA.x, sA.x, dA.y);
        const float4 p1 = make_float4(yA.y, sA.y, dB.x, yB.x);
        const float4 p2 = make_float4(sB.x, dB.y, yB.y, sB.y);
        __stcs(reinterpret_cast<float4*>(op) + 0, p0);
        __stcs(reinterpret_cast<float4*>(op) + 1, p1);
        __stcs(reinterpret_cast<float4*>(op) + 2, p2);
        op += (size_t)3 * IMG_W;
    }
}

__global__ __launch_bounds__(BLKT, 5)
void plane_fit_kernel(const float* __restrict__ x, float* __restrict__ out) {
    const int gx0 = (blockIdx.x * BLKT + threadIdx.x) * 4;
    const int gy0 = blockIdx.y * STRIP;
    const bool interior = (gx0 >= 4) && (gx0 + 7 < IMG_W);
    const bool vfast = (gy0 >= 3) && (gy0 + STRIP + 2 < IMG_H);
    if (vfast) strip_run<true >(x, out, gx0, gy0, interior);
    else       strip_run<false>(x, out, gx0, gy0, interior);
}

extern "C" void kernel_launch(void* const* d_in, const int* in_sizes, int n_in,
                              void* d_out, int out_size) {
    const float* x = (const float*)d_in[0];
    float* out = (float*)d_out;
    dim3 block(BLKT);
    dim3 grid(IMG_W / (BLKT * 4), IMG_H / STRIP);  // (4, 256) = 1024 blocks
    plane_fit_kernel<<<grid, block>>>(x, out);
}